// round 7
// baseline (speedup 1.0000x reference)
#include <cuda_runtime.h>

// E8 quantizer, closed form, lane-pair cooperative + persistent prefetch.
//
// Math (rounds 1-6): all 240 E8 roots have ||c||^2 = 2, so the softmax over
// -(dist^2)/T reduces to softmax(beta * x.c), beta = 2/0.3, and factorizes:
//  Type-1 (112 roots, +-1 at i, +-1 at j):  A_i = 2cosh(beta x_i)
//     denom1 = sum_{i<j} A_i A_j,   num1_d = (a_d b_d) * exclSum_d(A)
//  Type-2 (128 roots, (+-1/2)^8 even parity): a_i = 2cosh(bx_i/2), b_i = 2sinh(bx_i/2)
//     denom2 = (prod a + prod b)/2, num2_d = (b_d exclProd_d(a) + a_d exclProd_d(b))/4
//  with A = a^2 - 2.  16 EX2 + 1 RCP per point.  All-positive adds / sign-safe
//  muls -> no cancellation; +- root pairs => denom >= 1 => no max-shift.
//
// Mapping: lane pair (2k, 2k+1) = one point; each lane owns 4 dims = one
// float4 (perfect coalescing, 32 regs, 75%+ occupancy). R6 lesson: the
// shuffle chain was serial — fixed here by computing the within-half pair sum
// sigma_own locally so ALL FOUR shuffles are independent and issue together:
//   all-pairs sum_{i<j} A_i A_j = sig_own + sig_oth + S_own * S_oth.
// R4 lesson: persistent single wave + double-buffered prefetch hides the
// 577-cyc DRAM latency behind the previous point's compute.

#define BETA_HALF_LOG2E 4.8089834696568576f   // (2/0.3)/2 * log2(e)

__device__ __forceinline__ float ex2_approx(float x) {
    float y; asm("ex2.approx.ftz.f32 %0, %1;" : "=f"(y) : "f"(x)); return y;
}
__device__ __forceinline__ float rcp_approx(float x) {
    float y; asm("rcp.approx.ftz.f32 %0, %1;" : "=f"(y) : "f"(x)); return y;
}

__global__ void __launch_bounds__(256) e8_quantize_kernel(
    const float4* __restrict__ x4, float4* __restrict__ o4, int m, int stride)
{
    int g = blockIdx.x * blockDim.x + threadIdx.x;   // one float4 = half a point
    if (g >= m) return;          // m, stride multiples of 32 -> warp-uniform

    float4 v = x4[g];            // prime the pipeline

    for (;;) {
        int gn = g + stride;
        bool more = gn < m;      // warp-uniform (m, stride, warp-base all %32==0)
        float4 vn;
        if (more) vn = x4[gn];   // prefetch next half-point before computing

        float xi[4] = {v.x, v.y, v.z, v.w};

        float a[4], b[4], A[4];
#pragma unroll
        for (int i = 0; i < 4; i++) {
            float t  = xi[i] * BETA_HALF_LOG2E;
            float tn = xi[i] * (-BETA_HALF_LOG2E);
            float hp = ex2_approx(t);
            float hn = ex2_approx(tn);
            a[i] = hp + hn;
            b[i] = hp - hn;
            A[i] = fmaf(a[i], a[i], -2.0f);
        }

        // ---- own-half trees (4 elements) ----
        float s01 = A[0] + A[1], s23 = A[2] + A[3];
        float Sown = s01 + s23;
        float eo[4] = {A[1] + s23, A[0] + s23, s01 + A[3], s01 + A[2]};

        // within-half pair sum: sum_{i<j in half} A_i A_j (all positive)
        float sig = A[2] * A[3];
        sig = fmaf(A[0], A[1], sig);
        sig = fmaf(s01, s23, sig);

        float pa01 = a[0] * a[1], pa23 = a[2] * a[3];
        float Paown = pa01 * pa23;
        float epa[4] = {a[1] * pa23, a[0] * pa23, pa01 * a[3], pa01 * a[2]};

        float pb01 = b[0] * b[1], pb23 = b[2] * b[3];
        float Pbown = pb01 * pb23;
        float epb[4] = {b[1] * pb23, b[0] * pb23, pb01 * b[3], pb01 * b[2]};

        // ---- four independent shuffles, issued back-to-back ----
        float Soth  = __shfl_xor_sync(0xffffffffu, Sown,  1);
        float sigo  = __shfl_xor_sync(0xffffffffu, sig,   1);
        float Paoth = __shfl_xor_sync(0xffffffffu, Paown, 1);
        float Pboth = __shfl_xor_sync(0xffffffffu, Pbown, 1);

        // denominator: sum_{i<j,8} A_iA_j + (prod a + prod b)/2
        float D1 = fmaf(Sown, Soth, sig + sigo);
        float D  = fmaf(0.5f, fmaf(Paown, Paoth, Pbown * Pboth), D1);
        float rD = rcp_approx(D);

        // full exclusive quantities
        float PaQ = Paoth * 0.25f;
        float PbQ = Pboth * 0.25f;

        float o[4];
#pragma unroll
        for (int d = 0; d < 4; d++) {
            float eS    = eo[d] + Soth;                       // exclSum_d(A)
            float ea    = epa[d] * PaQ;                       // exclProd_d(a)/4
            float eb    = epb[d] * PbQ;                       // exclProd_d(b)/4
            float inner = fmaf(b[d], ea, a[d] * eb);
            float num   = fmaf(a[d] * b[d], eS, inner);
            o[d] = num * rD;
        }

        o4[g] = make_float4(o[0], o[1], o[2], o[3]);

        if (!more) break;
        g = gn; v = vn;
    }
}

extern "C" void kernel_launch(void* const* d_in, const int* in_sizes, int n_in,
                              void* d_out, int out_size) {
    const float4* x4 = (const float4*)d_in[0];   // [N, 8] fp32 = [2N] float4
    float4* o4 = (float4*)d_out;
    int n = in_sizes[0] / 8;
    int m = 2 * n;                               // half-points (float4 units)
    const int block = 256;
    int grid = 148 * 6;                          // persistent single wave
    int max_grid = (m + block - 1) / block;
    if (grid > max_grid) grid = max_grid;
    int stride = grid * block;                   // multiple of 32
    e8_quantize_kernel<<<grid, block>>>(x4, o4, m, stride);
}